// round 1
// baseline (speedup 1.0000x reference)
#include <cuda_runtime.h>

// Problem constants
#define NSAMP 4096
#define DIMD  128

// Scratch (alloc-free rule: __device__ globals)
__device__ float g_h [NSAMP * 640];   // tanh(z@Hw1+Hb1)
__device__ float g_w [NSAMP * 640];   // s*(1-h^2)*Hw2
__device__ float g_h1[NSAMP * 512];   // tanh(x@Aw1+Ab1)
__device__ float g_h2[NSAMP * 1024];  // tanh(h1@Aw2+Ab2)

__device__ __forceinline__ float fast_tanh(float x) {
    x = fminf(10.f, fmaxf(-10.f, x));
    float t = __expf(-2.f * x);
    return __fdividef(1.f - t, 1.f + t);
}

// ---------------------------------------------------------------------------
// Generic NN GEMM: C[M,N] = tanh(A[M,K] @ B[K,N] + bias[N])
// BM=64, BN=64, BK=16, 256 threads, 4x4 microtile
// ---------------------------------------------------------------------------
__global__ __launch_bounds__(256) void gemm_nn_tanh(
    const float* __restrict__ A, int lda,
    const float* __restrict__ B, int ldb,
    const float* __restrict__ bias,
    float* __restrict__ C, int ldc, int K)
{
    __shared__ float As[16][68];
    __shared__ float Bs[16][68];
    const int bm = blockIdx.y * 64;
    const int bn = blockIdx.x * 64;
    const int t  = threadIdx.x;
    const int tx = t & 15, ty = t >> 4;

    float acc[4][4];
#pragma unroll
    for (int i = 0; i < 4; i++)
#pragma unroll
        for (int j = 0; j < 4; j++) acc[i][j] = 0.f;

    for (int k0 = 0; k0 < K; k0 += 16) {
        // A tile 64x16 -> As[k][m]
#pragma unroll
        for (int i = t; i < 64 * 16; i += 256) {
            int m = i >> 4, k = i & 15;
            As[k][m] = A[(bm + m) * lda + k0 + k];
        }
        // B tile 16x64 -> Bs[k][n]
#pragma unroll
        for (int i = t; i < 16 * 64; i += 256) {
            int k = i >> 6, n = i & 63;
            Bs[k][n] = B[(k0 + k) * ldb + bn + n];
        }
        __syncthreads();
#pragma unroll
        for (int k = 0; k < 16; k++) {
            float a[4], b[4];
            *(float4*)a = *(const float4*)&As[k][ty * 4];
            *(float4*)b = *(const float4*)&Bs[k][tx * 4];
#pragma unroll
            for (int i = 0; i < 4; i++)
#pragma unroll
                for (int j = 0; j < 4; j++) acc[i][j] += a[i] * b[j];
        }
        __syncthreads();
    }
#pragma unroll
    for (int i = 0; i < 4; i++) {
        int row = bm + ty * 4 + i;
#pragma unroll
        for (int j = 0; j < 4; j++) {
            int col = bn + tx * 4 + j;
            C[row * ldc + col] = fast_tanh(acc[i][j] + bias[col]);
        }
    }
}

// ---------------------------------------------------------------------------
// K2: per-sample a2 reduction + backward weight vector w
//   a2 = h . Hw2 + Hb2 ; s = 1 - tanh(a2)^2 ; w = s*(1-h^2)*Hw2
// grid = NSAMP blocks of 128 threads
// ---------------------------------------------------------------------------
__global__ __launch_bounds__(128) void hgrad_mid(
    const float* __restrict__ Hw2, const float* __restrict__ Hb2)
{
    const int n = blockIdx.x;
    const int t = threadIdx.x;
    const float* hr = g_h + n * 640;
    float hv[5], w2[5];
    float acc = 0.f;
#pragma unroll
    for (int i = 0; i < 5; i++) {
        int j = t + i * 128;
        hv[i] = hr[j];
        w2[i] = Hw2[j];
        acc += hv[i] * w2[i];
    }
    __shared__ float red[128];
    red[t] = acc;
    __syncthreads();
#pragma unroll
    for (int s = 64; s > 0; s >>= 1) {
        if (t < s) red[t] += red[t + s];
        __syncthreads();
    }
    float o = fast_tanh(red[0] + Hb2[0]);
    float sfac = 1.f - o * o;
    float* wr = g_w + n * 640;
#pragma unroll
    for (int i = 0; i < 5; i++) {
        int j = t + i * 128;
        wr[j] = sfac * (1.f - hv[i] * hv[i]) * w2[i];
    }
}

// ---------------------------------------------------------------------------
// K3: g = w @ Hw1^T  (NT GEMM, K=640, N=256), writes out base:
//   out[n,k] = g (k<128) else -g
// ---------------------------------------------------------------------------
__global__ __launch_bounds__(256) void gemm_nt_grad(
    const float* __restrict__ Hw1, float* __restrict__ out)
{
    __shared__ float As[16][68];
    __shared__ float Bs[16][68];
    const int bm = blockIdx.y * 64;
    const int bn = blockIdx.x * 64;
    const int t  = threadIdx.x;
    const int tx = t & 15, ty = t >> 4;

    float acc[4][4];
#pragma unroll
    for (int i = 0; i < 4; i++)
#pragma unroll
        for (int j = 0; j < 4; j++) acc[i][j] = 0.f;

    for (int k0 = 0; k0 < 640; k0 += 16) {
#pragma unroll
        for (int i = t; i < 64 * 16; i += 256) {
            int m = i >> 4, k = i & 15;
            As[k][m] = g_w[(bm + m) * 640 + k0 + k];
        }
        // B tile: Bs[k][n] = Hw1[(bn+n)*640 + k0+k]
#pragma unroll
        for (int i = t; i < 64 * 16; i += 256) {
            int n = i >> 4, k = i & 15;
            Bs[k][n] = Hw1[(bn + n) * 640 + k0 + k];
        }
        __syncthreads();
#pragma unroll
        for (int k = 0; k < 16; k++) {
            float a[4], b[4];
            *(float4*)a = *(const float4*)&As[k][ty * 4];
            *(float4*)b = *(const float4*)&Bs[k][tx * 4];
#pragma unroll
            for (int i = 0; i < 4; i++)
#pragma unroll
                for (int j = 0; j < 4; j++) acc[i][j] += a[i] * b[j];
        }
        __syncthreads();
    }
#pragma unroll
    for (int i = 0; i < 4; i++) {
        int row = bm + ty * 4 + i;
#pragma unroll
        for (int j = 0; j < 4; j++) {
            int col = bn + tx * 4 + j;
            float v = acc[i][j];
            out[row * 256 + col] = (col < 128) ? v : -v;
        }
    }
}

// ---------------------------------------------------------------------------
// K6: fused big GEMM + tanh + u-contraction:
//   out[n, 128+i] += sum_jj tanh(h2[n] . Aw3[:, i*128+jj] + Ab3[i*128+jj]) * u[jj]
// block = (i, row-tile), BM=64, BN=128 (one full i-block), BK=16, 256 thr, 4x8
// ---------------------------------------------------------------------------
__global__ __launch_bounds__(256) void big_fused(
    const float* __restrict__ Aw3, const float* __restrict__ Ab3,
    const float* __restrict__ u, float* __restrict__ out)
{
    __shared__ float As[16][68];
    __shared__ float Bs[16][132];
    __shared__ float su[128];
    __shared__ float red[64][17];
    const int t  = threadIdx.x;
    const int tx = t & 15, ty = t >> 4;
    const int bm = blockIdx.y * 64;
    const int ib = blockIdx.x;       // which i (0..127)
    const int cb = ib * 128;         // column base in 16384

    if (t < 128) su[t] = u[t];

    float acc[4][8];
#pragma unroll
    for (int i = 0; i < 4; i++)
#pragma unroll
        for (int j = 0; j < 8; j++) acc[i][j] = 0.f;

    for (int k0 = 0; k0 < 1024; k0 += 16) {
#pragma unroll
        for (int i = t; i < 64 * 16; i += 256) {
            int m = i >> 4, k = i & 15;
            As[k][m] = g_h2[(bm + m) * 1024 + k0 + k];
        }
#pragma unroll
        for (int i = t; i < 16 * 128; i += 256) {
            int k = i >> 7, n = i & 127;
            Bs[k][n] = Aw3[(k0 + k) * 16384 + cb + n];
        }
        __syncthreads();
#pragma unroll
        for (int k = 0; k < 16; k++) {
            float a[4], b[8];
            *(float4*)a       = *(const float4*)&As[k][ty * 4];
            *(float4*)b       = *(const float4*)&Bs[k][tx * 8];
            *(float4*)(b + 4) = *(const float4*)&Bs[k][tx * 8 + 4];
#pragma unroll
            for (int i = 0; i < 4; i++)
#pragma unroll
                for (int j = 0; j < 8; j++) acc[i][j] += a[i] * b[j];
        }
        __syncthreads();
    }
    // epilogue: tanh + u-weighted column reduction
#pragma unroll
    for (int i = 0; i < 4; i++) {
        float s = 0.f;
#pragma unroll
        for (int j = 0; j < 8; j++) {
            int c = tx * 8 + j;
            s += fast_tanh(acc[i][j] + Ab3[cb + c]) * su[c];
        }
        red[ty * 4 + i][tx] = s;
    }
    __syncthreads();
    if (t < 64) {
        float s = 0.f;
#pragma unroll
        for (int j = 0; j < 16; j++) s += red[t][j];
        out[(bm + t) * 256 + 128 + ib] += s;
    }
}

// ---------------------------------------------------------------------------
extern "C" void kernel_launch(void* const* d_in, const int* in_sizes, int n_in,
                              void* d_out, int out_size)
{
    (void)in_sizes; (void)n_in; (void)out_size;
    const float* inp = (const float*)d_in[1];
    const float* Hw1 = (const float*)d_in[2];
    const float* Hb1 = (const float*)d_in[3];
    const float* Hw2 = (const float*)d_in[4];
    const float* Hb2 = (const float*)d_in[5];
    const float* Aw1 = (const float*)d_in[6];
    const float* Ab1 = (const float*)d_in[7];
    const float* Aw2 = (const float*)d_in[8];
    const float* Ab2 = (const float*)d_in[9];
    const float* Aw3 = (const float*)d_in[10];
    const float* Ab3 = (const float*)d_in[11];
    const float* u   = (const float*)d_in[12];
    float* out = (float*)d_out;

    static float* p_h  = nullptr;
    static float* p_h1 = nullptr;
    static float* p_h2 = nullptr;
    if (!p_h)  cudaGetSymbolAddress((void**)&p_h,  g_h);
    if (!p_h1) cudaGetSymbolAddress((void**)&p_h1, g_h1);
    if (!p_h2) cudaGetSymbolAddress((void**)&p_h2, g_h2);

    // H forward hidden: h = tanh(inp @ Hw1 + Hb1)   [4096 x 640], K=256
    gemm_nn_tanh<<<dim3(640 / 64, NSAMP / 64), 256>>>(
        inp, 2 * DIMD, Hw1, 640, Hb1, p_h, 640, 2 * DIMD);

    // per-sample scalar + backward weight vector
    hgrad_mid<<<NSAMP, 128>>>(Hw2, Hb2);

    // g = w @ Hw1^T -> out base (dx | -dv_g)
    gemm_nt_grad<<<dim3(256 / 64, NSAMP / 64), 256>>>(Hw1, out);

    // A net: h1 = tanh(x @ Aw1 + Ab1)  [4096 x 512], K=128 (x = first 128 cols of inp)
    gemm_nn_tanh<<<dim3(512 / 64, NSAMP / 64), 256>>>(
        inp, 2 * DIMD, Aw1, 512, Ab1, p_h1, 512, DIMD);

    // h2 = tanh(h1 @ Aw2 + Ab2)  [4096 x 1024], K=512
    gemm_nn_tanh<<<dim3(1024 / 64, NSAMP / 64), 256>>>(
        p_h1, 512, Aw2, 1024, Ab2, p_h2, 1024, 512);

    // fused: out[:,128:] += einsum(tanh(h2 @ Aw3 + Ab3), u)
    big_fused<<<dim3(128, NSAMP / 64), 256>>>(Aw3, Ab3, u, out);
}

// round 7
// speedup vs baseline: 4.8373x; 4.8373x over previous
#include <cuda_runtime.h>
#include <cuda_bf16.h>
#include <cstdint>

// Problem constants
#define NSAMP 4096
#define DIMD  128

// Scratch (alloc-free rule: __device__ globals)
__device__ float         g_h  [NSAMP * 640];    // tanh(z@Hw1+Hb1)
__device__ float         g_w  [NSAMP * 640];    // s*(1-h^2)*Hw2
__device__ float         g_h1 [NSAMP * 512];    // tanh(x@Aw1+Ab1)
__device__ __nv_bfloat16 g_h2b[NSAMP * 1024];   // tanh(h1@Aw2+Ab2) in bf16
__device__ __nv_bfloat16 g_w3b[16384 * 1024];   // Aw3^T in bf16, K-major [n][k]

__device__ __forceinline__ float fast_tanh(float x) {
    x = fminf(10.f, fmaxf(-10.f, x));
    float t = __expf(-2.f * x);
    return __fdividef(1.f - t, 1.f + t);
}

__device__ __forceinline__ uint32_t smem_to_u32(const void* p) {
    uint32_t a;
    asm("{ .reg .u64 t; cvta.to.shared.u64 t, %1; cvt.u32.u64 %0, t; }"
        : "=r"(a) : "l"(p));
    return a;
}

__device__ __forceinline__ void ldmatrix_x4(uint32_t& r0, uint32_t& r1,
                                            uint32_t& r2, uint32_t& r3,
                                            uint32_t addr) {
    asm volatile("ldmatrix.sync.aligned.m8n8.x4.shared.b16 {%0,%1,%2,%3}, [%4];"
                 : "=r"(r0), "=r"(r1), "=r"(r2), "=r"(r3) : "r"(addr));
}

__device__ __forceinline__ void mma16816(float* d,
                                         uint32_t a0, uint32_t a1, uint32_t a2, uint32_t a3,
                                         uint32_t b0, uint32_t b1) {
    asm volatile(
        "mma.sync.aligned.m16n8k16.row.col.f32.bf16.bf16.f32 "
        "{%0,%1,%2,%3}, {%4,%5,%6,%7}, {%8,%9}, {%0,%1,%2,%3};"
        : "+f"(d[0]), "+f"(d[1]), "+f"(d[2]), "+f"(d[3])
        : "r"(a0), "r"(a1), "r"(a2), "r"(a3), "r"(b0), "r"(b1));
}

// ===========================================================================
// Generic NN GEMM (fp32 out): C = tanh(A@B + bias)
// ===========================================================================
__global__ __launch_bounds__(256) void gemm_nn_tanh(
    const float* __restrict__ A, int lda,
    const float* __restrict__ B, int ldb,
    const float* __restrict__ bias,
    float* __restrict__ C, int ldc, int K)
{
    __shared__ float As[16][68];
    __shared__ float Bs[16][68];
    const int bm = blockIdx.y * 64;
    const int bn = blockIdx.x * 64;
    const int t  = threadIdx.x;
    const int tx = t & 15, ty = t >> 4;

    float acc[4][4];
#pragma unroll
    for (int i = 0; i < 4; i++)
#pragma unroll
        for (int j = 0; j < 4; j++) acc[i][j] = 0.f;

    for (int k0 = 0; k0 < K; k0 += 16) {
#pragma unroll
        for (int i = t; i < 64 * 16; i += 256) {
            int m = i >> 4, k = i & 15;
            As[k][m] = A[(bm + m) * lda + k0 + k];
        }
#pragma unroll
        for (int i = t; i < 16 * 64; i += 256) {
            int k = i >> 6, n = i & 63;
            Bs[k][n] = B[(k0 + k) * ldb + bn + n];
        }
        __syncthreads();
#pragma unroll
        for (int k = 0; k < 16; k++) {
            float a[4], b[4];
            *(float4*)a = *(const float4*)&As[k][ty * 4];
            *(float4*)b = *(const float4*)&Bs[k][tx * 4];
#pragma unroll
            for (int i = 0; i < 4; i++)
#pragma unroll
                for (int j = 0; j < 4; j++) acc[i][j] += a[i] * b[j];
        }
        __syncthreads();
    }
#pragma unroll
    for (int i = 0; i < 4; i++) {
        int row = bm + ty * 4 + i;
#pragma unroll
        for (int j = 0; j < 4; j++) {
            int col = bn + tx * 4 + j;
            C[row * ldc + col] = fast_tanh(acc[i][j] + bias[col]);
        }
    }
}

// Same GEMM but bf16 output (for h2)
__global__ __launch_bounds__(256) void gemm_nn_tanh_bf16(
    const float* __restrict__ A, int lda,
    const float* __restrict__ B, int ldb,
    const float* __restrict__ bias,
    __nv_bfloat16* __restrict__ C, int ldc, int K)
{
    __shared__ float As[16][68];
    __shared__ float Bs[16][68];
    const int bm = blockIdx.y * 64;
    const int bn = blockIdx.x * 64;
    const int t  = threadIdx.x;
    const int tx = t & 15, ty = t >> 4;

    float acc[4][4];
#pragma unroll
    for (int i = 0; i < 4; i++)
#pragma unroll
        for (int j = 0; j < 4; j++) acc[i][j] = 0.f;

    for (int k0 = 0; k0 < K; k0 += 16) {
#pragma unroll
        for (int i = t; i < 64 * 16; i += 256) {
            int m = i >> 4, k = i & 15;
            As[k][m] = A[(bm + m) * lda + k0 + k];
        }
#pragma unroll
        for (int i = t; i < 16 * 64; i += 256) {
            int k = i >> 6, n = i & 63;
            Bs[k][n] = B[(k0 + k) * ldb + bn + n];
        }
        __syncthreads();
#pragma unroll
        for (int k = 0; k < 16; k++) {
            float a[4], b[4];
            *(float4*)a = *(const float4*)&As[k][ty * 4];
            *(float4*)b = *(const float4*)&Bs[k][tx * 4];
#pragma unroll
            for (int i = 0; i < 4; i++)
#pragma unroll
                for (int j = 0; j < 4; j++) acc[i][j] += a[i] * b[j];
        }
        __syncthreads();
    }
#pragma unroll
    for (int i = 0; i < 4; i++) {
        int row = bm + ty * 4 + i;
#pragma unroll
        for (int j = 0; j < 4; j++) {
            int col = bn + tx * 4 + j;
            C[row * ldc + col] = __float2bfloat16(fast_tanh(acc[i][j] + bias[col]));
        }
    }
}

// ===========================================================================
// per-sample a2 reduction + backward weight vector w
// ===========================================================================
__global__ __launch_bounds__(128) void hgrad_mid(
    const float* __restrict__ Hw2, const float* __restrict__ Hb2)
{
    const int n = blockIdx.x;
    const int t = threadIdx.x;
    const float* hr = g_h + n * 640;
    float hv[5], w2[5];
    float acc = 0.f;
#pragma unroll
    for (int i = 0; i < 5; i++) {
        int j = t + i * 128;
        hv[i] = hr[j];
        w2[i] = Hw2[j];
        acc += hv[i] * w2[i];
    }
    __shared__ float red[128];
    red[t] = acc;
    __syncthreads();
#pragma unroll
    for (int s = 64; s > 0; s >>= 1) {
        if (t < s) red[t] += red[t + s];
        __syncthreads();
    }
    float o = fast_tanh(red[0] + Hb2[0]);
    float sfac = 1.f - o * o;
    float* wr = g_w + n * 640;
#pragma unroll
    for (int i = 0; i < 5; i++) {
        int j = t + i * 128;
        wr[j] = sfac * (1.f - hv[i] * hv[i]) * w2[i];
    }
}

// ===========================================================================
// g = w @ Hw1^T -> out base (dx | -dv_g)
// ===========================================================================
__global__ __launch_bounds__(256) void gemm_nt_grad(
    const float* __restrict__ Hw1, float* __restrict__ out)
{
    __shared__ float As[16][68];
    __shared__ float Bs[16][68];
    const int bm = blockIdx.y * 64;
    const int bn = blockIdx.x * 64;
    const int t  = threadIdx.x;
    const int tx = t & 15, ty = t >> 4;

    float acc[4][4];
#pragma unroll
    for (int i = 0; i < 4; i++)
#pragma unroll
        for (int j = 0; j < 4; j++) acc[i][j] = 0.f;

    for (int k0 = 0; k0 < 640; k0 += 16) {
#pragma unroll
        for (int i = t; i < 64 * 16; i += 256) {
            int m = i >> 4, k = i & 15;
            As[k][m] = g_w[(bm + m) * 640 + k0 + k];
        }
#pragma unroll
        for (int i = t; i < 64 * 16; i += 256) {
            int n = i >> 4, k = i & 15;
            Bs[k][n] = Hw1[(bn + n) * 640 + k0 + k];
        }
        __syncthreads();
#pragma unroll
        for (int k = 0; k < 16; k++) {
            float a[4], b[4];
            *(float4*)a = *(const float4*)&As[k][ty * 4];
            *(float4*)b = *(const float4*)&Bs[k][tx * 4];
#pragma unroll
            for (int i = 0; i < 4; i++)
#pragma unroll
                for (int j = 0; j < 4; j++) acc[i][j] += a[i] * b[j];
        }
        __syncthreads();
    }
#pragma unroll
    for (int i = 0; i < 4; i++) {
        int row = bm + ty * 4 + i;
#pragma unroll
        for (int j = 0; j < 4; j++) {
            int col = bn + tx * 4 + j;
            float v = acc[i][j];
            out[row * 256 + col] = (col < 128) ? v : -v;
        }
    }
}

// ===========================================================================
// Transpose+convert Aw3 [1024,16384] fp32 -> g_w3b [16384,1024] bf16
// ===========================================================================
__global__ __launch_bounds__(256) void transpose_w3(const float* __restrict__ Aw3)
{
    __shared__ float tile[32][33];
    const int n0 = blockIdx.x * 32;
    const int k0 = blockIdx.y * 32;
    for (int i = threadIdx.y; i < 32; i += 8)
        tile[i][threadIdx.x] = Aw3[(k0 + i) * 16384 + n0 + threadIdx.x];
    __syncthreads();
    for (int i = threadIdx.y; i < 32; i += 8)
        g_w3b[(n0 + i) * 1024 + k0 + threadIdx.x] = __float2bfloat16(tile[threadIdx.x][i]);
}

// ===========================================================================
// big_hmma: mma.sync bf16 GEMM + fused tanh + u-contraction
//   per CTA: M=128 samples, N=128 cols (one i-block), K=1024
//   8 warps as 4(M) x 2(N); warp tile 32x64; BK=64; cp.async double buffer
// ===========================================================================
// dynamic SMEM layout (relative to 1024-aligned base):
#define SM_A0   0        // 16 KB
#define SM_B0   16384    // 16 KB
#define SM_A1   32768    // 16 KB
#define SM_B1   49152    // 16 KB
#define SM_BIAS 65536    // 128 floats
#define SM_U    66048    // 128 floats
#define SM_RED  66560    // 128*2 floats
#define SM_END  67584
#define SMEM_BYTES (SM_END + 1024)

__global__ __launch_bounds__(256) void big_hmma(
    const float* __restrict__ Ab3, const float* __restrict__ u,
    float* __restrict__ out)
{
    extern __shared__ char smem_raw[];
    const uint32_t sb0 = smem_to_u32(smem_raw);
    const uint32_t sb  = (sb0 + 1023u) & ~1023u;
    char* sm8 = smem_raw + (sb - sb0);

    float* s_bias = (float*)(sm8 + SM_BIAS);
    float* s_u    = (float*)(sm8 + SM_U);
    float* s_red  = (float*)(sm8 + SM_RED);

    const int tid = threadIdx.x;
    const int l   = tid & 31;
    const int w   = tid >> 5;
    const int wm  = w >> 1;          // 0..3 (M warp)
    const int wn  = w & 1;           // 0..1 (N warp)
    const int bm  = blockIdx.x * 128;
    const int ib  = blockIdx.y;      // i-block 0..127
    const int cb  = ib * 128;

    if (tid < 128) {
        s_bias[tid] = Ab3[cb + tid];
        s_u[tid]    = u[tid];
    }

    const uint32_t abase[2] = { sb + SM_A0, sb + SM_A1 };
    const uint32_t bbase[2] = { sb + SM_B0, sb + SM_B1 };

    // global->smem load mapping: 256 thr, 16B each, 4 rows-passes
    const int seg = tid & 7;          // 16B segment within 128B row
    const int r0  = tid >> 3;         // 0..31
    const __nv_bfloat16* gA = g_h2b + (uint64_t)bm * 1024 + seg * 8;
    const __nv_bfloat16* gB = g_w3b + (uint64_t)cb * 1024 + seg * 8;

#define LOAD_CHUNK(c, bs) do { \
    uint32_t _ab = abase[bs], _bb = bbase[bs]; \
    const __nv_bfloat16* _ga = gA + (c) * 64; \
    const __nv_bfloat16* _gb = gB + (c) * 64; \
    _Pragma("unroll") \
    for (int i = 0; i < 4; i++) { \
        int row = r0 + 32 * i; \
        uint32_t dst = _ab + (uint32_t)row * 128 + (uint32_t)((seg ^ (row & 7)) << 4); \
        asm volatile("cp.async.cg.shared.global [%0], [%1], 16;" \
                     :: "r"(dst), "l"(_ga + (uint64_t)row * 1024) : "memory"); \
    } \
    _Pragma("unroll") \
    for (int i = 0; i < 4; i++) { \
        int row = r0 + 32 * i; \
        uint32_t dst = _bb + (uint32_t)row * 128 + (uint32_t)((seg ^ (row & 7)) << 4); \
        asm volatile("cp.async.cg.shared.global [%0], [%1], 16;" \
                     :: "r"(dst), "l"(_gb + (uint64_t)row * 1024) : "memory"); \
    } \
    asm volatile("cp.async.commit_group;" ::: "memory"); \
} while (0)

    // accumulators: [mt][nt][4]
    float d[2][8][4];
#pragma unroll
    for (int i = 0; i < 2; i++)
#pragma unroll
        for (int j = 0; j < 8; j++)
#pragma unroll
            for (int k = 0; k < 4; k++) d[i][j][k] = 0.f;

    // per-lane ldmatrix address precompute
    const int rowa      = wm * 32 + (l & 15);
    const uint32_t rbA0 = (uint32_t)rowa * 128;
    const uint32_t rbA1 = (uint32_t)(rowa + 16) * 128;
    const uint32_t sxA  = (uint32_t)(rowa & 7);
    const int segA0     = (l >> 4);
    const int rowb      = wn * 64 + (l & 7) + ((l >> 4) << 3);
    const uint32_t sxB  = (uint32_t)(rowb & 7);
    const int segB0     = (l >> 3) & 1;

    LOAD_CHUNK(0, 0);

    for (int c = 0; c < 16; c++) {
        asm volatile("cp.async.wait_group 0;" ::: "memory");
        __syncthreads();
        if (c + 1 < 16) LOAD_CHUNK(c + 1, (c + 1) & 1);

        const uint32_t aoff = abase[c & 1];
        const uint32_t boff = bbase[c & 1];
#pragma unroll
        for (int kk = 0; kk < 4; kk++) {
            const uint32_t sA = (uint32_t)(kk * 2 + segA0);
            uint32_t a0, a1, a2, a3, a4, a5, a6, a7;
            ldmatrix_x4(a0, a1, a2, a3, aoff + rbA0 + ((sA ^ sxA) << 4));
            ldmatrix_x4(a4, a5, a6, a7, aoff + rbA1 + ((sA ^ sxA) << 4));
            const uint32_t sB = (uint32_t)(kk * 2 + segB0);
#pragma unroll
            for (int p = 0; p < 4; p++) {
                uint32_t b0, b1, b2, b3;
                uint32_t rbB = (uint32_t)(rowb + p * 16) * 128;
                ldmatrix_x4(b0, b1, b2, b3, boff + rbB + ((sB ^ sxB) << 4));
                mma16816(d[0][2 * p],     a0, a1, a2, a3, b0, b1);
                mma16816(d[0][2 * p + 1], a0, a1, a2, a3, b2, b3);
                mma16816(d[1][2 * p],     a4, a5, a6, a7, b0, b1);
                mma16816(d[1][2 * p + 1], a4, a5, a6, a7, b2, b3);
            }
        }
    }
#undef LOAD_CHUNK

    // epilogue: tanh(acc + bias) * u, reduce over columns
#pragma unroll
    for (int mt = 0; mt < 2; mt++) {
        float sa = 0.f, sbx = 0.f;
#pragma unroll
        for (int nt = 0; nt < 8; nt++) {
            int c0 = wn * 64 + nt * 8 + (l & 3) * 2;
            float u0 = s_u[c0],    u1 = s_u[c0 + 1];
            float b0 = s_bias[c0], b1 = s_bias[c0 + 1];
            sa  += fast_tanh(d[mt][nt][0] + b0) * u0 + fast_tanh(d[mt][nt][1] + b1) * u1;
            sbx += fast_tanh(d[mt][nt][2] + b0) * u0 + fast_tanh(d[mt][nt][3] + b1) * u1;
        }
        sa  += __shfl_xor_sync(0xFFFFFFFFu, sa, 1);
        sa  += __shfl_xor_sync(0xFFFFFFFFu, sa, 2);
        sbx += __shfl_xor_sync(0xFFFFFFFFu, sbx, 1);
        sbx += __shfl_xor_sync(0xFFFFFFFFu, sbx, 2);
        if ((l & 3) == 0) {
            int r = wm * 32 + mt * 16 + (l >> 2);
            s_red[r * 2 + wn]       = sa;
            s_red[(r + 8) * 2 + wn] = sbx;
        }
    }
    __syncthreads();
    if (tid < 128) {
        float total = s_red[tid * 2] + s_red[tid * 2 + 1];
        out[(bm + tid) * 256 + 128 + ib] += total;
    }
}

// ===========================================================================
extern "C" void kernel_launch(void* const* d_in, const int* in_sizes, int n_in,
                              void* d_out, int out_size)
{
    (void)in_sizes; (void)n_in; (void)out_size;
    const float* inp = (const float*)d_in[1];
    const float* Hw1 = (const float*)d_in[2];
    const float* Hb1 = (const float*)d_in[3];
    const float* Hw2 = (const float*)d_in[4];
    const float* Hb2 = (const float*)d_in[5];
    const float* Aw1 = (const float*)d_in[6];
    const float* Ab1 = (const float*)d_in[7];
    const float* Aw2 = (const float*)d_in[8];
    const float* Ab2 = (const float*)d_in[9];
    const float* Aw3 = (const float*)d_in[10];
    const float* Ab3 = (const float*)d_in[11];
    const float* u   = (const float*)d_in[12];
    float* out = (float*)d_out;

    float* p_h  = nullptr;
    float* p_h1 = nullptr;
    __nv_bfloat16* p_h2b = nullptr;
    cudaGetSymbolAddress((void**)&p_h,   g_h);
    cudaGetSymbolAddress((void**)&p_h1,  g_h1);
    cudaGetSymbolAddress((void**)&p_h2b, g_h2b);

    cudaFuncSetAttribute(big_hmma, cudaFuncAttributeMaxDynamicSharedMemorySize, SMEM_BYTES);

    // Aw3 -> bf16 transposed (independent of everything else)
    transpose_w3<<<dim3(512, 32), dim3(32, 8)>>>(Aw3);

    // H forward hidden: h = tanh(inp @ Hw1 + Hb1)  [4096 x 640], K=256
    gemm_nn_tanh<<<dim3(640 / 64, NSAMP / 64), 256>>>(
        inp, 2 * DIMD, Hw1, 640, Hb1, p_h, 640, 2 * DIMD);

    // per-sample scalar + backward weight vector
    hgrad_mid<<<NSAMP, 128>>>(Hw2, Hb2);

    // g = w @ Hw1^T -> out base (dx | -dv_g)
    gemm_nt_grad<<<dim3(256 / 64, NSAMP / 64), 256>>>(Hw1, out);

    // A net: h1 = tanh(x @ Aw1 + Ab1)  [4096 x 512], K=128
    gemm_nn_tanh<<<dim3(512 / 64, NSAMP / 64), 256>>>(
        inp, 2 * DIMD, Aw1, 512, Ab1, p_h1, 512, DIMD);

    // h2 = tanh(h1 @ Aw2 + Ab2)  [4096 x 1024] in bf16, K=512
    gemm_nn_tanh_bf16<<<dim3(1024 / 64, NSAMP / 64), 256>>>(
        p_h1, 512, Aw2, 1024, Ab2, p_h2b, 1024, 512);

    // fused HMMA: out[:,128:] += einsum(tanh(h2 @ Aw3 + Ab3), u)
    big_hmma<<<dim3(NSAMP / 128, 128), 256, SMEM_BYTES>>>(Ab3, u, out);
}

// round 9
// speedup vs baseline: 9.7098x; 2.0073x over previous
#include <cuda_runtime.h>
#include <cuda_bf16.h>
#include <cstdint>

// Problem constants
#define NSAMP 4096
#define DIMD  128

// Scratch (alloc-free rule: __device__ globals)
__device__ float         g_h  [NSAMP * 640];    // tanh(z@Hw1+Hb1)
__device__ float         g_w  [NSAMP * 640];    // s*(1-h^2)*Hw2
__device__ float         g_dv [NSAMP * 128];    // einsum(tanh(gq), u)
__device__ __nv_bfloat16 g_xb [NSAMP * 128];    // x in bf16
__device__ __nv_bfloat16 g_h1b[NSAMP * 512];    // tanh(x@Aw1+Ab1) bf16
__device__ __nv_bfloat16 g_h2b[NSAMP * 1024];   // tanh(h1@Aw2+Ab2) bf16
__device__ __nv_bfloat16 g_w1b[512 * 128];      // Aw1^T bf16 [n][k]
__device__ __nv_bfloat16 g_w2b[1024 * 512];     // Aw2^T bf16 [n][k]
__device__ __nv_bfloat16 g_w3b[16384 * 1024];   // Aw3^T bf16 [n][k]

__device__ __forceinline__ float fast_tanh(float x) {
    x = fminf(10.f, fmaxf(-10.f, x));
    float t = __expf(-2.f * x);
    return __fdividef(1.f - t, 1.f + t);
}

__device__ __forceinline__ uint32_t smem_to_u32(const void* p) {
    uint32_t a;
    asm("{ .reg .u64 t; cvta.to.shared.u64 t, %1; cvt.u32.u64 %0, t; }"
        : "=r"(a) : "l"(p));
    return a;
}

__device__ __forceinline__ void ldmatrix_x4(uint32_t& r0, uint32_t& r1,
                                            uint32_t& r2, uint32_t& r3,
                                            uint32_t addr) {
    asm volatile("ldmatrix.sync.aligned.m8n8.x4.shared.b16 {%0,%1,%2,%3}, [%4];"
                 : "=r"(r0), "=r"(r1), "=r"(r2), "=r"(r3) : "r"(addr));
}

__device__ __forceinline__ void mma16816(float* d,
                                         uint32_t a0, uint32_t a1, uint32_t a2, uint32_t a3,
                                         uint32_t b0, uint32_t b1) {
    asm volatile(
        "mma.sync.aligned.m16n8k16.row.col.f32.bf16.bf16.f32 "
        "{%0,%1,%2,%3}, {%4,%5,%6,%7}, {%8,%9}, {%0,%1,%2,%3};"
        : "+f"(d[0]), "+f"(d[1]), "+f"(d[2]), "+f"(d[3])
        : "r"(a0), "r"(a1), "r"(a2), "r"(a3), "r"(b0), "r"(b1));
}

// ===========================================================================
// H forward GEMM (fp32, precision-critical): C = tanh(A@B + bias)
// ===========================================================================
__global__ __launch_bounds__(256) void gemm_nn_tanh(
    const float* __restrict__ A, int lda,
    const float* __restrict__ B, int ldb,
    const float* __restrict__ bias,
    float* __restrict__ C, int ldc, int K)
{
    __shared__ float As[16][68];
    __shared__ float Bs[16][68];
    const int bm = blockIdx.y * 64;
    const int bn = blockIdx.x * 64;
    const int t  = threadIdx.x;
    const int tx = t & 15, ty = t >> 4;

    float acc[4][4];
#pragma unroll
    for (int i = 0; i < 4; i++)
#pragma unroll
        for (int j = 0; j < 4; j++) acc[i][j] = 0.f;

    for (int k0 = 0; k0 < K; k0 += 16) {
#pragma unroll
        for (int i = t; i < 64 * 16; i += 256) {
            int m = i >> 4, k = i & 15;
            As[k][m] = A[(bm + m) * lda + k0 + k];
        }
#pragma unroll
        for (int i = t; i < 16 * 64; i += 256) {
            int k = i >> 6, n = i & 63;
            Bs[k][n] = B[(k0 + k) * ldb + bn + n];
        }
        __syncthreads();
#pragma unroll
        for (int k = 0; k < 16; k++) {
            float a[4], b[4];
            *(float4*)a = *(const float4*)&As[k][ty * 4];
            *(float4*)b = *(const float4*)&Bs[k][tx * 4];
#pragma unroll
            for (int i = 0; i < 4; i++)
#pragma unroll
                for (int j = 0; j < 4; j++) acc[i][j] += a[i] * b[j];
        }
        __syncthreads();
    }
#pragma unroll
    for (int i = 0; i < 4; i++) {
        int row = bm + ty * 4 + i;
#pragma unroll
        for (int j = 0; j < 4; j++) {
            int col = bn + tx * 4 + j;
            C[row * ldc + col] = fast_tanh(acc[i][j] + bias[col]);
        }
    }
}

// ===========================================================================
// per-sample a2 reduction + backward weight vector w
// ===========================================================================
__global__ __launch_bounds__(128) void hgrad_mid(
    const float* __restrict__ Hw2, const float* __restrict__ Hb2)
{
    const int n = blockIdx.x;
    const int t = threadIdx.x;
    const float* hr = g_h + n * 640;
    float hv[5], w2[5];
    float acc = 0.f;
#pragma unroll
    for (int i = 0; i < 5; i++) {
        int j = t + i * 128;
        hv[i] = hr[j];
        w2[i] = Hw2[j];
        acc += hv[i] * w2[i];
    }
    __shared__ float red[128];
    red[t] = acc;
    __syncthreads();
#pragma unroll
    for (int s = 64; s > 0; s >>= 1) {
        if (t < s) red[t] += red[t + s];
        __syncthreads();
    }
    float o = fast_tanh(red[0] + Hb2[0]);
    float sfac = 1.f - o * o;
    float* wr = g_w + n * 640;
#pragma unroll
    for (int i = 0; i < 5; i++) {
        int j = t + i * 128;
        wr[j] = sfac * (1.f - hv[i] * hv[i]) * w2[i];
    }
}

// ===========================================================================
// g = w @ Hw1^T -> out base (dx | -dv_g)  (fp32, precision-critical)
// ===========================================================================
__global__ __launch_bounds__(256) void gemm_nt_grad(
    const float* __restrict__ Hw1, float* __restrict__ out)
{
    __shared__ float As[16][68];
    __shared__ float Bs[16][68];
    const int bm = blockIdx.y * 64;
    const int bn = blockIdx.x * 64;
    const int t  = threadIdx.x;
    const int tx = t & 15, ty = t >> 4;

    float acc[4][4];
#pragma unroll
    for (int i = 0; i < 4; i++)
#pragma unroll
        for (int j = 0; j < 4; j++) acc[i][j] = 0.f;

    for (int k0 = 0; k0 < 640; k0 += 16) {
#pragma unroll
        for (int i = t; i < 64 * 16; i += 256) {
            int m = i >> 4, k = i & 15;
            As[k][m] = g_w[(bm + m) * 640 + k0 + k];
        }
#pragma unroll
        for (int i = t; i < 64 * 16; i += 256) {
            int n = i >> 4, k = i & 15;
            Bs[k][n] = Hw1[(bn + n) * 640 + k0 + k];
        }
        __syncthreads();
#pragma unroll
        for (int k = 0; k < 16; k++) {
            float a[4], b[4];
            *(float4*)a = *(const float4*)&As[k][ty * 4];
            *(float4*)b = *(const float4*)&Bs[k][tx * 4];
#pragma unroll
            for (int i = 0; i < 4; i++)
#pragma unroll
                for (int j = 0; j < 4; j++) acc[i][j] += a[i] * b[j];
        }
        __syncthreads();
    }
#pragma unroll
    for (int i = 0; i < 4; i++) {
        int row = bm + ty * 4 + i;
#pragma unroll
        for (int j = 0; j < 4; j++) {
            int col = bn + tx * 4 + j;
            float v = acc[i][j];
            out[row * 256 + col] = (col < 128) ? v : -v;
        }
    }
}

// ===========================================================================
// Generic transpose+convert: src[R,C] fp32 row-major -> dst[C,R] bf16
// ===========================================================================
__global__ __launch_bounds__(256) void transT(
    const float* __restrict__ src, __nv_bfloat16* __restrict__ dst,
    int R, int C)
{
    __shared__ float tile[32][33];
    const int c0 = blockIdx.x * 32;
    const int r0 = blockIdx.y * 32;
    for (int i = threadIdx.y; i < 32; i += 8)
        tile[i][threadIdx.x] = src[(r0 + i) * C + c0 + threadIdx.x];
    __syncthreads();
    for (int i = threadIdx.y; i < 32; i += 8)
        dst[(c0 + i) * R + r0 + threadIdx.x] = __float2bfloat16(tile[threadIdx.x][i]);
}

// x (first 128 cols of inp) -> bf16
__global__ void conv_x(const float* __restrict__ inp)
{
    int m = blockIdx.x, k = threadIdx.x;
    g_xb[m * 128 + k] = __float2bfloat16(inp[m * 256 + k]);
}

// out[:,128+i] += g_dv
__global__ void add_dv_k(float* __restrict__ out)
{
    int idx = blockIdx.x * 256 + threadIdx.x;
    int m = idx >> 7, i = idx & 127;
    out[m * 256 + 128 + i] += g_dv[idx];
}

// ===========================================================================
// hmma_tanh: C[M,N](bf16) = tanh(A[M,K](bf16) @ BT[N,K](bf16)^T + bias)
//   CTA 128x128, 8 warps (4Mx2N), BK=64 double-buffered cp.async
// ===========================================================================
#define SMG_A0   0
#define SMG_B0   16384
#define SMG_A1   32768
#define SMG_B1   49152
#define SMG_BIAS 65536
#define SMG_END  66048
#define SMEM_G   (SMG_END + 1024)

__global__ __launch_bounds__(256) void hmma_tanh(
    const __nv_bfloat16* __restrict__ A,
    const __nv_bfloat16* __restrict__ BT,
    const float* __restrict__ bias,
    __nv_bfloat16* __restrict__ C,
    int K, int N, int nchunks)
{
    extern __shared__ char smem_raw[];
    const uint32_t sb0 = smem_to_u32(smem_raw);
    const uint32_t sb  = (sb0 + 1023u) & ~1023u;
    char* sm8 = smem_raw + (sb - sb0);
    float* s_bias = (float*)(sm8 + SMG_BIAS);

    const int tid = threadIdx.x;
    const int l   = tid & 31;
    const int w   = tid >> 5;
    const int wm  = w >> 1;
    const int wn  = w & 1;
    const int bm  = blockIdx.x * 128;
    const int bn  = blockIdx.y * 128;

    if (tid < 128) s_bias[tid] = bias[bn + tid];

    const uint32_t abase[2] = { sb + SMG_A0, sb + SMG_A1 };
    const uint32_t bbase[2] = { sb + SMG_B0, sb + SMG_B1 };

    const int seg = tid & 7;
    const int r0  = tid >> 3;
    const __nv_bfloat16* gA = A  + (uint64_t)bm * K + seg * 8;
    const __nv_bfloat16* gB = BT + (uint64_t)bn * K + seg * 8;

#define LOAD_CHUNK_G(c, bs) do { \
    uint32_t _ab = abase[bs], _bb = bbase[bs]; \
    const __nv_bfloat16* _ga = gA + (c) * 64; \
    const __nv_bfloat16* _gb = gB + (c) * 64; \
    _Pragma("unroll") \
    for (int i = 0; i < 4; i++) { \
        int row = r0 + 32 * i; \
        uint32_t dst = _ab + (uint32_t)row * 128 + (uint32_t)((seg ^ (row & 7)) << 4); \
        asm volatile("cp.async.cg.shared.global [%0], [%1], 16;" \
                     :: "r"(dst), "l"(_ga + (uint64_t)row * K) : "memory"); \
    } \
    _Pragma("unroll") \
    for (int i = 0; i < 4; i++) { \
        int row = r0 + 32 * i; \
        uint32_t dst = _bb + (uint32_t)row * 128 + (uint32_t)((seg ^ (row & 7)) << 4); \
        asm volatile("cp.async.cg.shared.global [%0], [%1], 16;" \
                     :: "r"(dst), "l"(_gb + (uint64_t)row * K) : "memory"); \
    } \
    asm volatile("cp.async.commit_group;" ::: "memory"); \
} while (0)

    float d[2][8][4];
#pragma unroll
    for (int i = 0; i < 2; i++)
#pragma unroll
        for (int j = 0; j < 8; j++)
#pragma unroll
            for (int k = 0; k < 4; k++) d[i][j][k] = 0.f;

    const int rowa      = wm * 32 + (l & 15);
    const uint32_t rbA0 = (uint32_t)rowa * 128;
    const uint32_t rbA1 = (uint32_t)(rowa + 16) * 128;
    const uint32_t sxA  = (uint32_t)(rowa & 7);
    const int segA0     = (l >> 4);
    const int rowb      = wn * 64 + (l & 7) + ((l >> 4) << 3);
    const uint32_t sxB  = (uint32_t)(rowb & 7);
    const int segB0     = (l >> 3) & 1;

    LOAD_CHUNK_G(0, 0);

    for (int c = 0; c < nchunks; c++) {
        asm volatile("cp.async.wait_group 0;" ::: "memory");
        __syncthreads();
        if (c + 1 < nchunks) LOAD_CHUNK_G(c + 1, (c + 1) & 1);

        const uint32_t aoff = abase[c & 1];
        const uint32_t boff = bbase[c & 1];
#pragma unroll
        for (int kk = 0; kk < 4; kk++) {
            const uint32_t sA = (uint32_t)(kk * 2 + segA0);
            uint32_t a0, a1, a2, a3, a4, a5, a6, a7;
            ldmatrix_x4(a0, a1, a2, a3, aoff + rbA0 + ((sA ^ sxA) << 4));
            ldmatrix_x4(a4, a5, a6, a7, aoff + rbA1 + ((sA ^ sxA) << 4));
            const uint32_t sB = (uint32_t)(kk * 2 + segB0);
#pragma unroll
            for (int p = 0; p < 4; p++) {
                uint32_t b0, b1, b2, b3;
                uint32_t rbB = (uint32_t)(rowb + p * 16) * 128;
                ldmatrix_x4(b0, b1, b2, b3, boff + rbB + ((sB ^ sxB) << 4));
                mma16816(d[0][2 * p],     a0, a1, a2, a3, b0, b1);
                mma16816(d[0][2 * p + 1], a0, a1, a2, a3, b2, b3);
                mma16816(d[1][2 * p],     a4, a5, a6, a7, b0, b1);
                mma16816(d[1][2 * p + 1], a4, a5, a6, a7, b2, b3);
            }
        }
    }
#undef LOAD_CHUNK_G

    // epilogue: tanh(acc + bias) -> bf16 store
#pragma unroll
    for (int mt = 0; mt < 2; mt++) {
        const int r = bm + wm * 32 + mt * 16 + (l >> 2);
#pragma unroll
        for (int nt = 0; nt < 8; nt++) {
            int cl = wn * 64 + nt * 8 + (l & 3) * 2;
            int cg = bn + cl;
            float b0 = s_bias[cl], b1 = s_bias[cl + 1];
            __nv_bfloat162 p0, p1;
            p0.x = __float2bfloat16(fast_tanh(d[mt][nt][0] + b0));
            p0.y = __float2bfloat16(fast_tanh(d[mt][nt][1] + b1));
            p1.x = __float2bfloat16(fast_tanh(d[mt][nt][2] + b0));
            p1.y = __float2bfloat16(fast_tanh(d[mt][nt][3] + b1));
            *(__nv_bfloat162*)(C + (uint64_t)r * N + cg)       = p0;
            *(__nv_bfloat162*)(C + (uint64_t)(r + 8) * N + cg) = p1;
        }
    }
}

// ===========================================================================
// big_hmma: bf16 GEMM + fused tanh + u-contraction -> g_dv
// ===========================================================================
#define SM_A0   0
#define SM_B0   16384
#define SM_A1   32768
#define SM_B1   49152
#define SM_BIAS 65536
#define SM_U    66048
#define SM_RED  66560
#define SM_END  67584
#define SMEM_BYTES (SM_END + 1024)

__global__ __launch_bounds__(256) void big_hmma(
    const float* __restrict__ Ab3, const float* __restrict__ u)
{
    extern __shared__ char smem_raw[];
    const uint32_t sb0 = smem_to_u32(smem_raw);
    const uint32_t sb  = (sb0 + 1023u) & ~1023u;
    char* sm8 = smem_raw + (sb - sb0);

    float* s_bias = (float*)(sm8 + SM_BIAS);
    float* s_u    = (float*)(sm8 + SM_U);
    float* s_red  = (float*)(sm8 + SM_RED);

    const int tid = threadIdx.x;
    const int l   = tid & 31;
    const int w   = tid >> 5;
    const int wm  = w >> 1;
    const int wn  = w & 1;
    const int bm  = blockIdx.x * 128;
    const int ib  = blockIdx.y;
    const int cb  = ib * 128;

    if (tid < 128) {
        s_bias[tid] = Ab3[cb + tid];
        s_u[tid]    = u[tid];
    }

    const uint32_t abase[2] = { sb + SM_A0, sb + SM_A1 };
    const uint32_t bbase[2] = { sb + SM_B0, sb + SM_B1 };

    const int seg = tid & 7;
    const int r0  = tid >> 3;
    const __nv_bfloat16* gA = g_h2b + (uint64_t)bm * 1024 + seg * 8;
    const __nv_bfloat16* gB = g_w3b + (uint64_t)cb * 1024 + seg * 8;

#define LOAD_CHUNK(c, bs) do { \
    uint32_t _ab = abase[bs], _bb = bbase[bs]; \
    const __nv_bfloat16* _ga = gA + (c) * 64; \
    const __nv_bfloat16* _gb = gB + (c) * 64; \
    _Pragma("unroll") \
    for (int i = 0; i < 4; i++) { \
        int row = r0 + 32 * i; \
        uint32_t dst = _ab + (uint32_t)row * 128 + (uint32_t)((seg ^ (row & 7)) << 4); \
        asm volatile("cp.async.cg.shared.global [%0], [%1], 16;" \
                     :: "r"(dst), "l"(_ga + (uint64_t)row * 1024) : "memory"); \
    } \
    _Pragma("unroll") \
    for (int i = 0; i < 4; i++) { \
        int row = r0 + 32 * i; \
        uint32_t dst = _bb + (uint32_t)row * 128 + (uint32_t)((seg ^ (row & 7)) << 4); \
        asm volatile("cp.async.cg.shared.global [%0], [%1], 16;" \
                     :: "r"(dst), "l"(_gb + (uint64_t)row * 1024) : "memory"); \
    } \
    asm volatile("cp.async.commit_group;" ::: "memory"); \
} while (0)

    float d[2][8][4];
#pragma unroll
    for (int i = 0; i < 2; i++)
#pragma unroll
        for (int j = 0; j < 8; j++)
#pragma unroll
            for (int k = 0; k < 4; k++) d[i][j][k] = 0.f;

    const int rowa      = wm * 32 + (l & 15);
    const uint32_t rbA0 = (uint32_t)rowa * 128;
    const uint32_t rbA1 = (uint32_t)(rowa + 16) * 128;
    const uint32_t sxA  = (uint32_t)(rowa & 7);
    const int segA0     = (l >> 4);
    const int rowb      = wn * 64 + (l & 7) + ((l >> 4) << 3);
    const uint32_t sxB  = (uint32_t)(rowb & 7);
    const int segB0     = (l >> 3) & 1;

    LOAD_CHUNK(0, 0);

    for (int c = 0; c < 16; c++) {
        asm volatile("cp.async.wait_group 0;" ::: "memory");
        __syncthreads();
        if (c + 1 < 16) LOAD_CHUNK(c + 1, (c + 1) & 1);

        const uint32_t aoff = abase[c & 1];
        const uint32_t boff = bbase[c & 1];
#pragma unroll
        for (int kk = 0; kk < 4; kk++) {
            const uint32_t sA = (uint32_t)(kk * 2 + segA0);
            uint32_t a0, a1, a2, a3, a4, a5, a6, a7;
            ldmatrix_x4(a0, a1, a2, a3, aoff + rbA0 + ((sA ^ sxA) << 4));
            ldmatrix_x4(a4, a5, a6, a7, aoff + rbA1 + ((sA ^ sxA) << 4));
            const uint32_t sB = (uint32_t)(kk * 2 + segB0);
#pragma unroll
            for (int p = 0; p < 4; p++) {
                uint32_t b0, b1, b2, b3;
                uint32_t rbB = (uint32_t)(rowb + p * 16) * 128;
                ldmatrix_x4(b0, b1, b2, b3, boff + rbB + ((sB ^ sxB) << 4));
                mma16816(d[0][2 * p],     a0, a1, a2, a3, b0, b1);
                mma16816(d[0][2 * p + 1], a0, a1, a2, a3, b2, b3);
                mma16816(d[1][2 * p],     a4, a5, a6, a7, b0, b1);
                mma16816(d[1][2 * p + 1], a4, a5, a6, a7, b2, b3);
            }
        }
    }
#undef LOAD_CHUNK

    // epilogue: tanh(acc + bias) * u, reduce over columns
#pragma unroll
    for (int mt = 0; mt < 2; mt++) {
        float sa = 0.f, sbx = 0.f;
#pragma unroll
        for (int nt = 0; nt < 8; nt++) {
            int c0 = wn * 64 + nt * 8 + (l & 3) * 2;
            float u0 = s_u[c0],    u1 = s_u[c0 + 1];
            float b0 = s_bias[c0], b1 = s_bias[c0 + 1];
            sa  += fast_tanh(d[mt][nt][0] + b0) * u0 + fast_tanh(d[mt][nt][1] + b1) * u1;
            sbx += fast_tanh(d[mt][nt][2] + b0) * u0 + fast_tanh(d[mt][nt][3] + b1) * u1;
        }
        sa  += __shfl_xor_sync(0xFFFFFFFFu, sa, 1);
        sa  += __shfl_xor_sync(0xFFFFFFFFu, sa, 2);
        sbx += __shfl_xor_sync(0xFFFFFFFFu, sbx, 1);
        sbx += __shfl_xor_sync(0xFFFFFFFFu, sbx, 2);
        if ((l & 3) == 0) {
            int r = wm * 32 + mt * 16 + (l >> 2);
            s_red[r * 2 + wn]       = sa;
            s_red[(r + 8) * 2 + wn] = sbx;
        }
    }
    __syncthreads();
    if (tid < 128) {
        g_dv[(bm + tid) * 128 + ib] = s_red[tid * 2] + s_red[tid * 2 + 1];
    }
}

// ===========================================================================
extern "C" void kernel_launch(void* const* d_in, const int* in_sizes, int n_in,
                              void* d_out, int out_size)
{
    (void)in_sizes; (void)n_in; (void)out_size;
    const float* inp = (const float*)d_in[1];
    const float* Hw1 = (const float*)d_in[2];
    const float* Hb1 = (const float*)d_in[3];
    const float* Hw2 = (const float*)d_in[4];
    const float* Hb2 = (const float*)d_in[5];
    const float* Aw1 = (const float*)d_in[6];
    const float* Ab1 = (const float*)d_in[7];
    const float* Aw2 = (const float*)d_in[8];
    const float* Ab2 = (const float*)d_in[9];
    const float* Aw3 = (const float*)d_in[10];
    const float* Ab3 = (const float*)d_in[11];
    const float* u   = (const float*)d_in[12];
    float* out = (float*)d_out;

    static float* p_h = nullptr;
    static __nv_bfloat16 *p_xb = nullptr, *p_h1b = nullptr, *p_h2b = nullptr;
    static __nv_bfloat16 *p_w1b = nullptr, *p_w2b = nullptr, *p_w3b = nullptr;
    static cudaStream_t s2 = nullptr;
    static cudaEvent_t evF = nullptr, evJ = nullptr;
    if (!p_h) {
        cudaGetSymbolAddress((void**)&p_h,   g_h);
        cudaGetSymbolAddress((void**)&p_xb,  g_xb);
        cudaGetSymbolAddress((void**)&p_h1b, g_h1b);
        cudaGetSymbolAddress((void**)&p_h2b, g_h2b);
        cudaGetSymbolAddress((void**)&p_w1b, g_w1b);
        cudaGetSymbolAddress((void**)&p_w2b, g_w2b);
        cudaGetSymbolAddress((void**)&p_w3b, g_w3b);
        cudaStreamCreateWithFlags(&s2, cudaStreamNonBlocking);
        cudaEventCreateWithFlags(&evF, cudaEventDisableTiming);
        cudaEventCreateWithFlags(&evJ, cudaEventDisableTiming);
    }

    cudaFuncSetAttribute(big_hmma,  cudaFuncAttributeMaxDynamicSharedMemorySize, SMEM_BYTES);
    cudaFuncSetAttribute(hmma_tanh, cudaFuncAttributeMaxDynamicSharedMemorySize, SMEM_G);

    // ---- fork: s2 runs the A-path ----
    cudaEventRecord(evF, 0);
    cudaStreamWaitEvent(s2, evF, 0);

    // A-path (stream s2): conversions -> h1 -> h2 -> big GEMM -> g_dv
    conv_x<<<NSAMP, 128, 0, s2>>>(inp);
    transT<<<dim3(512 / 32, 128 / 32),   dim3(32, 8), 0, s2>>>(Aw1, p_w1b, 128, 512);
    hmma_tanh<<<dim3(NSAMP / 128, 4), 256, SMEM_G, s2>>>(
        p_xb, p_w1b, Ab1, p_h1b, 128, 512, 2);
    transT<<<dim3(1024 / 32, 512 / 32),  dim3(32, 8), 0, s2>>>(Aw2, p_w2b, 512, 1024);
    hmma_tanh<<<dim3(NSAMP / 128, 8), 256, SMEM_G, s2>>>(
        p_h1b, p_w2b, Ab2, p_h2b, 512, 1024, 8);
    transT<<<dim3(16384 / 32, 1024 / 32), dim3(32, 8), 0, s2>>>(Aw3, p_w3b, 1024, 16384);
    big_hmma<<<dim3(NSAMP / 128, 128), 256, SMEM_BYTES, s2>>>(Ab3, u);

    // H-path (main stream): h -> w -> g = w @ Hw1^T -> out base
    gemm_nn_tanh<<<dim3(640 / 64, NSAMP / 64), 256>>>(
        inp, 2 * DIMD, Hw1, 640, Hb1, p_h, 640, 2 * DIMD);
    hgrad_mid<<<NSAMP, 128>>>(Hw2, Hb2);
    gemm_nt_grad<<<dim3(256 / 64, NSAMP / 64), 256>>>(Hw1, out);

    // ---- join, then add einsum into out ----
    cudaEventRecord(evJ, s2);
    cudaStreamWaitEvent(0, evJ, 0);
    add_dv_k<<<(NSAMP * 128) / 256, 256>>>(out);
}